// round 10
// baseline (speedup 1.0000x reference)
#include <cuda_runtime.h>

#define DD     64
#define NUSERS 100000
#define NENT   100000
#define NNODES 200000
#define EKG    1500000
#define EPREF  1500000
#define NNZK   1000000

// Scratch (no allocations allowed) — device globals.
__device__ float g_entA[(size_t)NENT * DD];
__device__ float g_entB[(size_t)NENT * DD];
__device__ float g_nodeA[(size_t)NNODES * DD];
__device__ float g_nodeB[(size_t)NNODES * DD];
__device__ float g_uacc[(size_t)NUSERS * DD];
__device__ float g_scaleE[NENT];
__device__ float g_scaleN[NNODES];
__device__ int   g_cntE[NENT];
__device__ int   g_cntN[NNODES];

// ---------------------------------------------------------------------------
// Degree counts — edge lists are fixed, so compute ONCE per launch.
// ---------------------------------------------------------------------------
__global__ __launch_bounds__(256) void count_k(
    const int* __restrict__ head, const int* __restrict__ ehead,
    int* __restrict__ cntE, int* __restrict__ cntN)
{
    unsigned tid = blockIdx.x * 256u + threadIdx.x;
    if (tid < (unsigned)EKG) {
        atomicAdd(cntE + head[tid], 1);
    } else if (tid < (unsigned)(EKG + EPREF)) {
        atomicAdd(cntN + ehead[tid - EKG], 1);
    }
}

// ---------------------------------------------------------------------------
// KG edges: out[head] += ent[tail] * scale[tail] * weight[etype-1]
// 16 threads per edge, one float4 each. scale==null means 1.0 (hop 0).
// ---------------------------------------------------------------------------
__global__ __launch_bounds__(256) void kg_scatter_k(
    const float* __restrict__ ent, const float* __restrict__ scale,
    const int* __restrict__ head, const int* __restrict__ tail,
    const int* __restrict__ etype, const float* __restrict__ w,
    float* __restrict__ out)
{
    unsigned tid = blockIdx.x * 256u + threadIdx.x;
    if (tid >= (unsigned)EKG * 16u) return;
    unsigned e = tid >> 4, c = tid & 15u;
    int h = head[e], t = tail[e], r = etype[e] - 1;
    float s = scale ? scale[t] : 1.f;
    float4 v  = reinterpret_cast<const float4*>(ent + (size_t)t * DD)[c];
    float4 ww = reinterpret_cast<const float4*>(w + (size_t)r * DD)[c];
    v.x *= ww.x * s; v.y *= ww.y * s; v.z *= ww.z * s; v.w *= ww.w * s;
    atomicAdd(reinterpret_cast<float4*>(out + (size_t)h * DD) + c, v);
}

// ---------------------------------------------------------------------------
// Preference edges: src from user-part (node sums * scaleN) or entity table
// (* scaleE). Null scales mean 1.0 (hop 0 reads raw embeddings).
// ---------------------------------------------------------------------------
__global__ __launch_bounds__(256) void pref_scatter_k(
    const float* __restrict__ userpart, const float* __restrict__ scaleN,
    const float* __restrict__ entpart, const float* __restrict__ scaleE,
    const int* __restrict__ ehead, const int* __restrict__ etail,
    const int* __restrict__ etype, const float* __restrict__ w,
    float* __restrict__ out)
{
    unsigned tid = blockIdx.x * 256u + threadIdx.x;
    if (tid >= (unsigned)EPREF * 16u) return;
    unsigned e = tid >> 4, c = tid & 15u;
    int h = ehead[e], t = etail[e], r = etype[e];
    const float* src; float s;
    if (t < NUSERS) {
        src = userpart + (size_t)t * DD;
        s = scaleN ? scaleN[t] : 1.f;
    } else {
        int te = t - NUSERS;
        src = entpart + (size_t)te * DD;
        s = scaleE ? scaleE[te] : 1.f;
    }
    float4 v  = reinterpret_cast<const float4*>(src)[c];
    float4 ww = reinterpret_cast<const float4*>(w + (size_t)r * DD)[c];
    v.x *= ww.x * s; v.y *= ww.y * s; v.z *= ww.z * s; v.w *= ww.w * s;
    atomicAdd(reinterpret_cast<float4*>(out + (size_t)h * DD) + c, v);
}

// ---------------------------------------------------------------------------
// Interact: uacc[rows] += vals * entSum[cols] / cntE[cols]  (mean folded in).
// ---------------------------------------------------------------------------
__global__ __launch_bounds__(256) void interact_k(
    const float* __restrict__ entSum, const int* __restrict__ cntE,
    const int* __restrict__ rows, const int* __restrict__ cols,
    const float* __restrict__ vals, float* __restrict__ uacc)
{
    unsigned tid = blockIdx.x * 256u + threadIdx.x;
    if (tid >= (unsigned)NNZK * 16u) return;
    unsigned e = tid >> 4, c = tid & 15u;
    int r = rows[e], col = cols[e];
    float s = vals[e] / fmaxf((float)cntE[col], 1.f);
    float4 v = reinterpret_cast<const float4*>(entSum + (size_t)col * DD)[c];
    v.x *= s; v.y *= s; v.z *= s; v.w *= s;
    atomicAdd(reinterpret_cast<float4*>(uacc + (size_t)r * DD) + c, v);
}

// ---------------------------------------------------------------------------
// Fused finalize: for each row of {entity sums, node sums, user acc} compute
// inv = 1/max(||sum||, 1e-12) (count cancels: normalize(mean) == sum/||sum||),
// write the scale array (for next hop's scatters), and write residual
// res = base + sum*inv. NO writeback into the accumulator buffers.
// One warp per row, 32 lanes x float2.
// ---------------------------------------------------------------------------
__global__ __launch_bounds__(256) void finalize_all_k(
    const float* __restrict__ entBuf, float* __restrict__ scaleE,
    float* __restrict__ entCopy,                    // last hop: gcn_res ent slice
    const float* __restrict__ nodeBuf, float* __restrict__ scaleN,
    const float* __restrict__ nodeBaseU,            // node residual base, user part
    const float* __restrict__ nodeBaseE,            // node residual base, ent part
    float* __restrict__ nodeRes,
    const float* __restrict__ uaccBuf,
    const float* __restrict__ userBase, float* __restrict__ userRes)
{
    int idx = blockIdx.x * 8 + (int)(threadIdx.x >> 5);
    int lane = threadIdx.x & 31;
    const int TOT = NENT + NNODES + NUSERS;
    if (idx >= TOT) return;

    const float* buf; const float* base; float* res; float* cpy; float* sOut;
    if (idx < NENT) {
        buf = entBuf + (size_t)idx * DD;
        sOut = scaleE + idx;
        base = nullptr; res = nullptr;
        cpy = entCopy ? entCopy + (size_t)idx * DD : nullptr;
    } else if (idx < NENT + NNODES) {
        int r = idx - NENT;
        buf = nodeBuf + (size_t)r * DD;
        sOut = scaleN + r;
        base = (r < NUSERS) ? nodeBaseU + (size_t)r * DD
                            : nodeBaseE + (size_t)(r - NUSERS) * DD;
        res = nodeRes + (size_t)r * DD; cpy = nullptr;
    } else {
        int r = idx - NENT - NNODES;
        buf = uaccBuf + (size_t)r * DD;
        sOut = nullptr;
        base = userBase + (size_t)r * DD;
        res = userRes + (size_t)r * DD; cpy = nullptr;
    }

    float2 v = reinterpret_cast<const float2*>(buf)[lane];
    float ss = v.x * v.x + v.y * v.y;
    #pragma unroll
    for (int o = 16; o > 0; o >>= 1) ss += __shfl_xor_sync(0xffffffffu, ss, o);
    float inv = 1.f / fmaxf(sqrtf(ss), 1e-12f);
    if (sOut && lane == 0) *sOut = inv;
    v.x *= inv; v.y *= inv;
    if (res) {
        float2 b = reinterpret_cast<const float2*>(base)[lane];
        b.x += v.x; b.y += v.y;
        reinterpret_cast<float2*>(res)[lane] = b;
    }
    if (cpy)
        reinterpret_cast<float2*>(cpy)[lane] = v;
}

// ---------------------------------------------------------------------------
extern "C" void kernel_launch(void* const* d_in, const int* in_sizes, int n_in,
                              void* d_out, int out_size)
{
    (void)in_sizes; (void)n_in; (void)out_size;
    const float* user_emb   = (const float*)d_in[0];
    const float* entity_emb = (const float*)d_in[1];
    const float* weight     = (const float*)d_in[2];
    const float* exweight   = (const float*)d_in[3];
    const float* ivals      = (const float*)d_in[4];
    const int*   eidx       = (const int*)d_in[5];
    const int*   etype      = (const int*)d_in[6];
    const int*   xeidx      = (const int*)d_in[7];
    const int*   xetype     = (const int*)d_in[8];
    const int*   iidx       = (const int*)d_in[9];
    float* out = (float*)d_out;

    const int* head  = eidx;
    const int* tail  = eidx + EKG;
    const int* ehead = xeidx;
    const int* etail = xeidx + EPREF;
    const int* rows  = iidx;
    const int* cols  = iidx + NNZK;

    float *entA, *entB, *nodeA, *nodeB, *uacc, *scaleE, *scaleN;
    int *cntE, *cntN;
    cudaGetSymbolAddress((void**)&entA,   g_entA);
    cudaGetSymbolAddress((void**)&entB,   g_entB);
    cudaGetSymbolAddress((void**)&nodeA,  g_nodeA);
    cudaGetSymbolAddress((void**)&nodeB,  g_nodeB);
    cudaGetSymbolAddress((void**)&uacc,   g_uacc);
    cudaGetSymbolAddress((void**)&scaleE, g_scaleE);
    cudaGetSymbolAddress((void**)&scaleN, g_scaleN);
    cudaGetSymbolAddress((void**)&cntE,   g_cntE);
    cudaGetSymbolAddress((void**)&cntN,   g_cntN);

    // Output layout: gcn_res = [user_res ; ent_final], then node_res.
    float* user_res = out;                                   // NUSERS*DD
    float* ent_out  = out + (size_t)NUSERS * DD;             // NENT*DD
    float* node_res = out + (size_t)(NUSERS + NENT) * DD;    // NNODES*DD

    const int B = 256;
    const int KG_GRID  = (int)(((size_t)EKG * 16 + B - 1) / B);
    const int PR_GRID  = (int)(((size_t)EPREF * 16 + B - 1) / B);
    const int INT_GRID = (int)(((size_t)NNZK * 16 + B - 1) / B);
    const int FIN_GRID = (NENT + NNODES + NUSERS + 7) / 8;
    const int CNT_GRID = (EKG + EPREF + B - 1) / B;

    // Degree counts: fixed across hops — compute once.
    cudaMemsetAsync(cntE, 0, sizeof(int) * NENT);
    cudaMemsetAsync(cntN, 0, sizeof(int) * NNODES);
    count_k<<<CNT_GRID, B>>>(head, ehead, cntE, cntN);

    const float* entCur   = entity_emb;  // entity sums read this hop
    const float* userPart = user_emb;    // user slice (node sums) read this hop
    const float* sE = nullptr;           // scale for entCur rows
    const float* sN = nullptr;           // scale for userPart rows
    float* entNext  = entA;
    float* nodeNext = nodeA;

    for (int hop = 0; hop < 2; hop++) {
        cudaMemsetAsync(entNext,  0, sizeof(float) * (size_t)NENT * DD);
        cudaMemsetAsync(nodeNext, 0, sizeof(float) * (size_t)NNODES * DD);
        cudaMemsetAsync(uacc,     0, sizeof(float) * (size_t)NUSERS * DD);

        kg_scatter_k<<<KG_GRID, B>>>(
            entCur, sE, head, tail, etype, weight, entNext);
        pref_scatter_k<<<PR_GRID, B>>>(
            userPart, sN, entCur, sE, ehead, etail, xetype, exweight, nodeNext);
        interact_k<<<INT_GRID, B>>>(entNext, cntE, rows, cols, ivals, uacc);

        // hop 0: residual base = original embeddings; hop 1: in-place on d_out.
        const float* nbU = (hop == 0) ? user_emb   : node_res;
        const float* nbE = (hop == 0) ? entity_emb : node_res + (size_t)NUSERS * DD;
        const float* ubB = (hop == 0) ? user_emb   : user_res;

        finalize_all_k<<<FIN_GRID, B>>>(
            entNext, scaleE, (hop == 1) ? ent_out : nullptr,
            nodeNext, scaleN, nbU, nbE, node_res,
            uacc, ubB, user_res);

        entCur   = entNext;   // next hop reads these sums...
        userPart = nodeNext;  // ...scaled by the scale arrays just written
        sE = scaleE;
        sN = scaleN;
        entNext  = entB;
        nodeNext = nodeB;
    }
}

// round 17
// speedup vs baseline: 1.6209x; 1.6209x over previous
#include <cuda_runtime.h>

#define DD     64
#define NUSERS 100000
#define NENT   100000
#define NNODES 200000
#define EKG    1500000
#define EPREF  1500000
#define NNZK   1000000

// Scratch (no allocations allowed) — device globals.
__device__ float g_entA[(size_t)NENT * DD];
__device__ float g_entB[(size_t)NENT * DD];
__device__ float g_nodeA[(size_t)NNODES * DD];
__device__ float g_nodeB[(size_t)NNODES * DD];
__device__ float g_uacc[(size_t)NUSERS * DD];
__device__ int   g_cntE[NENT];
__device__ int   g_cntN[NNODES];
__device__ float g_invE[NENT];
__device__ float g_invN[NNODES];

// ---------------------------------------------------------------------------
// Degree counts — edge lists are fixed, so compute ONCE per launch.
// ---------------------------------------------------------------------------
__global__ __launch_bounds__(256) void count_k(
    const int* __restrict__ head, const int* __restrict__ ehead,
    int* __restrict__ cntE, int* __restrict__ cntN)
{
    unsigned tid = blockIdx.x * 256u + threadIdx.x;
    if (tid < (unsigned)EKG) {
        atomicAdd(cntE + head[tid], 1);
    } else if (tid < (unsigned)(EKG + EPREF)) {
        atomicAdd(cntN + ehead[tid - EKG], 1);
    }
}

__global__ __launch_bounds__(256) void inv_k(
    const int* __restrict__ cntE, const int* __restrict__ cntN,
    float* __restrict__ invE, float* __restrict__ invN)
{
    unsigned tid = blockIdx.x * 256u + threadIdx.x;
    if (tid < (unsigned)NENT)
        invE[tid] = 1.f / fmaxf((float)cntE[tid], 1.f);
    if (tid < (unsigned)NNODES)
        invN[tid] = 1.f / fmaxf((float)cntN[tid], 1.f);
}

// ---------------------------------------------------------------------------
// KG edges: out[head] += ent[tail] * weight[etype-1]
// 16 threads per edge-pair; each thread handles edges e and e+EKG/2
// (two independent gather->RED chains, MLP=2). No count atomics.
// ---------------------------------------------------------------------------
__global__ __launch_bounds__(256) void kg_scatter_k(
    const float* __restrict__ ent, const int* __restrict__ head,
    const int* __restrict__ tail, const int* __restrict__ etype,
    const float* __restrict__ w, float* __restrict__ out)
{
    const unsigned HALF = EKG / 2;
    unsigned tid = blockIdx.x * 256u + threadIdx.x;
    if (tid >= HALF * 16u) return;
    unsigned e0 = tid >> 4, c = tid & 15u;
    unsigned e1 = e0 + HALF;

    int h0 = head[e0], h1 = head[e1];
    int t0 = tail[e0], t1 = tail[e1];
    int r0 = etype[e0] - 1, r1 = etype[e1] - 1;

    float4 a0 = reinterpret_cast<const float4*>(ent + (size_t)t0 * DD)[c];
    float4 a1 = reinterpret_cast<const float4*>(ent + (size_t)t1 * DD)[c];
    float4 w0 = reinterpret_cast<const float4*>(w + (size_t)r0 * DD)[c];
    float4 w1 = reinterpret_cast<const float4*>(w + (size_t)r1 * DD)[c];
    a0.x *= w0.x; a0.y *= w0.y; a0.z *= w0.z; a0.w *= w0.w;
    a1.x *= w1.x; a1.y *= w1.y; a1.z *= w1.z; a1.w *= w1.w;

    atomicAdd(reinterpret_cast<float4*>(out + (size_t)h0 * DD) + c, a0);
    atomicAdd(reinterpret_cast<float4*>(out + (size_t)h1 * DD) + c, a1);
}

// ---------------------------------------------------------------------------
// Preference edges, same 2-edge-per-thread shape. src row from user-part
// (node table) or entity table — both already normalized for hop > 0.
// ---------------------------------------------------------------------------
__global__ __launch_bounds__(256) void pref_scatter_k(
    const float* __restrict__ userpart, const float* __restrict__ entpart,
    const int* __restrict__ ehead, const int* __restrict__ etail,
    const int* __restrict__ etype, const float* __restrict__ w,
    float* __restrict__ out)
{
    const unsigned HALF = EPREF / 2;
    unsigned tid = blockIdx.x * 256u + threadIdx.x;
    if (tid >= HALF * 16u) return;
    unsigned e0 = tid >> 4, c = tid & 15u;
    unsigned e1 = e0 + HALF;

    int h0 = ehead[e0], h1 = ehead[e1];
    int t0 = etail[e0], t1 = etail[e1];
    int r0 = etype[e0], r1 = etype[e1];

    const float* s0 = (t0 < NUSERS) ? (userpart + (size_t)t0 * DD)
                                    : (entpart + (size_t)(t0 - NUSERS) * DD);
    const float* s1 = (t1 < NUSERS) ? (userpart + (size_t)t1 * DD)
                                    : (entpart + (size_t)(t1 - NUSERS) * DD);

    float4 a0 = reinterpret_cast<const float4*>(s0)[c];
    float4 a1 = reinterpret_cast<const float4*>(s1)[c];
    float4 w0 = reinterpret_cast<const float4*>(w + (size_t)r0 * DD)[c];
    float4 w1 = reinterpret_cast<const float4*>(w + (size_t)r1 * DD)[c];
    a0.x *= w0.x; a0.y *= w0.y; a0.z *= w0.z; a0.w *= w0.w;
    a1.x *= w1.x; a1.y *= w1.y; a1.z *= w1.z; a1.w *= w1.w;

    atomicAdd(reinterpret_cast<float4*>(out + (size_t)h0 * DD) + c, a0);
    atomicAdd(reinterpret_cast<float4*>(out + (size_t)h1 * DD) + c, a1);
}

// ---------------------------------------------------------------------------
// Interact: uacc[rows] += vals * entSum[cols] * invE[cols]  (mean folded in,
// reciprocal precomputed). 2 independent edges per thread.
// ---------------------------------------------------------------------------
__global__ __launch_bounds__(256) void interact_k(
    const float* __restrict__ entSum, const float* __restrict__ invE,
    const int* __restrict__ rows, const int* __restrict__ cols,
    const float* __restrict__ vals, float* __restrict__ uacc)
{
    const unsigned HALF = NNZK / 2;
    unsigned tid = blockIdx.x * 256u + threadIdx.x;
    if (tid >= HALF * 16u) return;
    unsigned e0 = tid >> 4, c = tid & 15u;
    unsigned e1 = e0 + HALF;

    int r0 = rows[e0], r1 = rows[e1];
    int c0 = cols[e0], c1 = cols[e1];
    float s0 = vals[e0] * invE[c0];
    float s1 = vals[e1] * invE[c1];

    float4 v0 = reinterpret_cast<const float4*>(entSum + (size_t)c0 * DD)[c];
    float4 v1 = reinterpret_cast<const float4*>(entSum + (size_t)c1 * DD)[c];
    v0.x *= s0; v0.y *= s0; v0.z *= s0; v0.w *= s0;
    v1.x *= s1; v1.y *= s1; v1.z *= s1; v1.w *= s1;

    atomicAdd(reinterpret_cast<float4*>(uacc + (size_t)r0 * DD) + c, v0);
    atomicAdd(reinterpret_cast<float4*>(uacc + (size_t)r1 * DD) + c, v1);
}

// ---------------------------------------------------------------------------
// Fused finalize over entity (mean+norm+writeback, optional copy-out), node
// (mean+norm+writeback+residual) and user (norm+writeback+residual).
// Residual: resOut = base + v (hop0 base = original emb, hop1 in-place).
// One warp per row, 32 lanes x float2.
// ---------------------------------------------------------------------------
__global__ __launch_bounds__(256) void finalize_all_k(
    float* __restrict__ entBuf, const float* __restrict__ invE,
    float* __restrict__ entCopy,                    // last hop: gcn_res ent slice
    float* __restrict__ nodeBuf, const float* __restrict__ invN,
    const float* __restrict__ nodeBaseU,            // node residual base, user part
    const float* __restrict__ nodeBaseE,            // node residual base, ent part
    float* __restrict__ nodeRes,
    float* __restrict__ uaccBuf,
    const float* __restrict__ userBase, float* __restrict__ userRes)
{
    int idx = blockIdx.x * 8 + (int)(threadIdx.x >> 5);
    int lane = threadIdx.x & 31;
    const int TOT = NENT + NNODES + NUSERS;
    if (idx >= TOT) return;

    float* buf; float minv; const float* base; float* res; float* cpy;
    if (idx < NENT) {
        buf = entBuf + (size_t)idx * DD; minv = invE[idx];
        base = nullptr; res = nullptr;
        cpy = entCopy ? entCopy + (size_t)idx * DD : nullptr;
    } else if (idx < NENT + NNODES) {
        int r = idx - NENT;
        buf = nodeBuf + (size_t)r * DD; minv = invN[r];
        base = (r < NUSERS) ? nodeBaseU + (size_t)r * DD
                            : nodeBaseE + (size_t)(r - NUSERS) * DD;
        res = nodeRes + (size_t)r * DD; cpy = nullptr;
    } else {
        int r = idx - NENT - NNODES;
        buf = uaccBuf + (size_t)r * DD; minv = 1.f;
        base = userBase + (size_t)r * DD;
        res = userRes + (size_t)r * DD; cpy = nullptr;
    }

    float2* p = reinterpret_cast<float2*>(buf) + lane;
    float2 v = *p;
    v.x *= minv; v.y *= minv;
    float ss = v.x * v.x + v.y * v.y;
    #pragma unroll
    for (int o = 16; o > 0; o >>= 1) ss += __shfl_xor_sync(0xffffffffu, ss, o);
    float inv = 1.f / fmaxf(sqrtf(ss), 1e-12f);
    v.x *= inv; v.y *= inv;
    *p = v;                       // writeback: next hop reads normalized rows
    if (res) {
        float2 b = reinterpret_cast<const float2*>(base)[lane];
        b.x += v.x; b.y += v.y;
        reinterpret_cast<float2*>(res)[lane] = b;
    }
    if (cpy)
        reinterpret_cast<float2*>(cpy)[lane] = v;
}

// ---------------------------------------------------------------------------
extern "C" void kernel_launch(void* const* d_in, const int* in_sizes, int n_in,
                              void* d_out, int out_size)
{
    (void)in_sizes; (void)n_in; (void)out_size;
    const float* user_emb   = (const float*)d_in[0];
    const float* entity_emb = (const float*)d_in[1];
    const float* weight     = (const float*)d_in[2];
    const float* exweight   = (const float*)d_in[3];
    const float* ivals      = (const float*)d_in[4];
    const int*   eidx       = (const int*)d_in[5];
    const int*   etype      = (const int*)d_in[6];
    const int*   xeidx      = (const int*)d_in[7];
    const int*   xetype     = (const int*)d_in[8];
    const int*   iidx       = (const int*)d_in[9];
    float* out = (float*)d_out;

    const int* head  = eidx;
    const int* tail  = eidx + EKG;
    const int* ehead = xeidx;
    const int* etail = xeidx + EPREF;
    const int* rows  = iidx;
    const int* cols  = iidx + NNZK;

    float *entA, *entB, *nodeA, *nodeB, *uacc, *invE, *invN;
    int *cntE, *cntN;
    cudaGetSymbolAddress((void**)&entA,  g_entA);
    cudaGetSymbolAddress((void**)&entB,  g_entB);
    cudaGetSymbolAddress((void**)&nodeA, g_nodeA);
    cudaGetSymbolAddress((void**)&nodeB, g_nodeB);
    cudaGetSymbolAddress((void**)&uacc,  g_uacc);
    cudaGetSymbolAddress((void**)&invE,  g_invE);
    cudaGetSymbolAddress((void**)&invN,  g_invN);
    cudaGetSymbolAddress((void**)&cntE,  g_cntE);
    cudaGetSymbolAddress((void**)&cntN,  g_cntN);

    // Output layout: gcn_res = [user_res ; ent_final], then node_res.
    float* user_res = out;                                   // NUSERS*DD
    float* ent_out  = out + (size_t)NUSERS * DD;             // NENT*DD
    float* node_res = out + (size_t)(NUSERS + NENT) * DD;    // NNODES*DD

    const int B = 256;
    const int KG_GRID  = (int)(((size_t)(EKG / 2) * 16 + B - 1) / B);
    const int PR_GRID  = (int)(((size_t)(EPREF / 2) * 16 + B - 1) / B);
    const int INT_GRID = (int)(((size_t)(NNZK / 2) * 16 + B - 1) / B);
    const int FIN_GRID = (NENT + NNODES + NUSERS + 7) / 8;
    const int CNT_GRID = (EKG + EPREF + B - 1) / B;
    const int INV_GRID = (NNODES + B - 1) / B;

    // Degree counts + reciprocals: fixed across hops — compute once.
    cudaMemsetAsync(cntE, 0, sizeof(int) * NENT);
    cudaMemsetAsync(cntN, 0, sizeof(int) * NNODES);
    count_k<<<CNT_GRID, B>>>(head, ehead, cntE, cntN);
    inv_k<<<INV_GRID, B>>>(cntE, cntN, invE, invN);

    const float* entCur   = entity_emb;  // entity table read this hop
    const float* userPart = user_emb;    // user slice of node table read this hop
    float* entNext  = entA;
    float* nodeNext = nodeA;

    for (int hop = 0; hop < 2; hop++) {
        cudaMemsetAsync(entNext,  0, sizeof(float) * (size_t)NENT * DD);
        cudaMemsetAsync(nodeNext, 0, sizeof(float) * (size_t)NNODES * DD);
        cudaMemsetAsync(uacc,     0, sizeof(float) * (size_t)NUSERS * DD);

        kg_scatter_k<<<KG_GRID, B>>>(
            entCur, head, tail, etype, weight, entNext);
        pref_scatter_k<<<PR_GRID, B>>>(
            userPart, entCur, ehead, etail, xetype, exweight, nodeNext);
        interact_k<<<INT_GRID, B>>>(entNext, invE, rows, cols, ivals, uacc);

        // hop 0: residual base = original embeddings; hop 1: in-place on d_out.
        const float* nbU = (hop == 0) ? user_emb   : node_res;
        const float* nbE = (hop == 0) ? entity_emb : node_res + (size_t)NUSERS * DD;
        const float* ubB = (hop == 0) ? user_emb   : user_res;

        finalize_all_k<<<FIN_GRID, B>>>(
            entNext, invE, (hop == 1) ? ent_out : nullptr,
            nodeNext, invN, nbU, nbE, node_res,
            uacc, ubB, user_res);

        entCur   = entNext;
        userPart = nodeNext;   // next hop's user slice = normalized node table
        entNext  = entB;
        nodeNext = nodeB;
    }
}